// round 12
// baseline (speedup 1.0000x reference)
#include <cuda_runtime.h>
#include <math.h>
#include <stdint.h>

#define Bb 128
#define Mm 200
#define Ss 20
#define Qq 20
#define Vv 50000
#define Dd 128
#define NT 4          // max_hops + 1 tables

// -------- device scratch (static allocation; no cudaMalloc allowed) --------
__device__ float g_u[Bb * Dd];                              // 64 KB
__device__ float g_mt[(long)NT * Bb * Mm * Dd];             // 52.4 MB
__device__ float g_rowsum[Bb];                              // softmax denominators

// ============================================================
// Kernel 1: mt[t][b][i][d] = sum_s E[t][story[b,i,s]][d] + T[t][i][d]
// One warp per (t,b,i), table-major grid (one table hot in L2 at a time).
// ============================================================
#define SS_WPB 8
__global__ void __launch_bounds__(SS_WPB * 32) k_story_sums(
        const int* __restrict__ story,
        const float* __restrict__ E,
        const float* __restrict__ T) {
    long gw = (long)blockIdx.x * SS_WPB + (threadIdx.x >> 5);
    int lane = threadIdx.x & 31;
    int t = (int)(gw / ((long)Bb * Mm));
    int rem = (int)(gw - (long)t * Bb * Mm);
    int b = rem / Mm, i = rem - b * Mm;

    int tok = (lane < Ss) ? story[((long)b * Mm + i) * Ss + lane] : 0;

    const float4* Et = (const float4*)(E + (long)t * Vv * Dd);
    float4 acc = ((const float4*)(T + ((long)t * Mm + i) * Dd))[lane];
#pragma unroll
    for (int s = 0; s < Ss; s++) {
        int id = __shfl_sync(0xffffffffu, tok, s);
        float4 r = Et[(long)id * 32 + lane];
        acc.x += r.x; acc.y += r.y; acc.z += r.z; acc.w += r.w;
    }
    ((float4*)(g_mt + (((long)t * Bb + b) * Mm + i) * Dd))[lane] = acc;
}

// ============================================================
// Kernel 2: query embedding + all 3 hops fused. grid=B, block=1024.
// Also zeroes g_rowsum (block 0) for the epilogue atomics.
// ============================================================
__global__ void __launch_bounds__(1024) k_hops(
        const int* __restrict__ query,
        const float* __restrict__ E) {
    __shared__ float su[Dd];
    __shared__ float sc[Mm];
    __shared__ float red[32];
    __shared__ float bc[2];
    __shared__ float op[1024];
    int b = blockIdx.x, tid = threadIdx.x;
    int w = tid >> 5, lane = tid & 31;

    if (b == 0 && tid < Bb) g_rowsum[tid] = 0.f;   // reset denominators

    // ---- u = sum over query tokens of E[0] rows (fused) ----
    {
        __shared__ int q[Qq];
        if (tid < Qq) q[tid] = query[b * Qq + tid];
        __syncthreads();
        if (tid < Dd) {
            float acc = 0.f;
#pragma unroll
            for (int i = 0; i < Qq; i++)
                acc += E[(long)q[i] * Dd + tid];
            su[tid] = acc;
        }
    }
    __syncthreads();

    for (int hop = 0; hop < NT - 1; hop++) {
        const float* mt = g_mt + (((long)hop * Bb + b) * Mm) * Dd;
        float4 uu = ((const float4*)su)[lane];
        for (int i = w; i < Mm; i += 32) {
            const float4* row = (const float4*)(mt + (long)i * Dd);
            float4 r = row[lane];
            float p = r.x * uu.x + r.y * uu.y + r.z * uu.z + r.w * uu.w;
#pragma unroll
            for (int o = 16; o; o >>= 1) p += __shfl_xor_sync(0xffffffffu, p, o);
            if (lane == 0) sc[i] = p;
        }
        __syncthreads();

        float v = (tid < Mm) ? sc[tid] : -INFINITY;
        float m = v;
#pragma unroll
        for (int o = 16; o; o >>= 1) m = fmaxf(m, __shfl_xor_sync(0xffffffffu, m, o));
        if (lane == 0) red[w] = m;
        __syncthreads();
        if (w == 0) {
            float t = red[lane];
#pragma unroll
            for (int o = 16; o; o >>= 1) t = fmaxf(t, __shfl_xor_sync(0xffffffffu, t, o));
            if (lane == 0) bc[0] = t;
        }
        __syncthreads();
        float e = (tid < Mm) ? expf(v - bc[0]) : 0.f;
        float s = e;
#pragma unroll
        for (int o = 16; o; o >>= 1) s += __shfl_xor_sync(0xffffffffu, s, o);
        if (lane == 0) red[w] = s;
        __syncthreads();
        if (w == 0) {
            float t = red[lane];
#pragma unroll
            for (int o = 16; o; o >>= 1) t += __shfl_xor_sync(0xffffffffu, t, o);
            if (lane == 0) bc[1] = 1.f / t;
        }
        __syncthreads();
        if (tid < Mm) sc[tid] = e * bc[1];
        __syncthreads();

        const float* mtn = g_mt + (((long)(hop + 1) * Bb + b) * Mm) * Dd;
        int part = tid >> 7, d = tid & 127;
        float acc = 0.f;
        int i0 = part * 25;
#pragma unroll
        for (int i = i0; i < i0 + 25; i++)
            acc += sc[i] * mtn[(long)i * Dd + d];
        op[tid] = acc;
        __syncthreads();
        if (tid < Dd) {
            float o = 0.f;
#pragma unroll
            for (int p = 0; p < 8; p++) o += op[p * 128 + tid];
            su[tid] += o;
        }
        __syncthreads();
    }
    if (tid < Dd) g_u[b * Dd + tid] = su[tid];
}

// ============================================================
// tf32 split via bitmask (LOP3 + FADD; no cvt).
// ============================================================
__device__ __forceinline__ void tf32_mask_split(float x, uint32_t& hi, uint32_t& lo) {
    hi = __float_as_uint(x) & 0xFFFFE000u;
    lo = __float_as_uint(x - __uint_as_float(hi));
}
#define MMA_TF32(c, a0, a1, a2, a3, b0, b1) \
    asm volatile("mma.sync.aligned.m16n8k8.row.col.f32.tf32.tf32.f32 " \
        "{%0,%1,%2,%3}, {%4,%5,%6,%7}, {%8,%9}, {%0,%1,%2,%3};" \
        : "+f"((c)[0]), "+f"((c)[1]), "+f"((c)[2]), "+f"((c)[3]) \
        : "r"(a0), "r"(a1), "r"(a2), "r"(a3), "r"(b0), "r"(b1))

// ============================================================
// Kernel 3: ahat = u @ E3^T, 3xTF32 mma (mask-split), K chunked 2x64,
// 4 CTAs/SM (<=64 regs; acc32+frag20+addr ~62 fits). Epilogue: ahat
// stores + exp row-sum atomics.
// ============================================================
#define KC 64
#define CPITCH (KC + 4)
#define GSM4 ((128 + 64) * CPITCH * 4)   // 52,224 B

__global__ void __launch_bounds__(256, 4)
k_gemm_mma(const float* __restrict__ E3, float* __restrict__ ahat,
           int do_proba) {
    extern __shared__ float sm[];
    float* sA = sm;                     // [128][CPITCH]
    float* sB = sm + 128 * CPITCH;      // [64][CPITCH]
    int tid = threadIdx.x, lane = tid & 31, wid = tid >> 5;
    int wm = wid & 3, wn = wid >> 2;
    int v0 = blockIdx.x * 64;

    float acc[2][4][4];
#pragma unroll
    for (int i = 0; i < 2; i++)
#pragma unroll
        for (int j = 0; j < 4; j++)
#pragma unroll
            for (int k = 0; k < 4; k++) acc[i][j][k] = 0.f;

    int g = lane >> 2, tg = lane & 3;
    const float4* gu = (const float4*)g_u;
    const float4* ge = (const float4*)E3;

#pragma unroll
    for (int kc = 0; kc < 2; kc++) {
#pragma unroll
        for (int it = 0; it < 8; it++) {
            int e = tid + it * 256;
            int row = e >> 4, c4 = e & 15;
            *(float4*)(sA + row * CPITCH + c4 * 4) = gu[row * 32 + kc * 16 + c4];
        }
#pragma unroll
        for (int it = 0; it < 4; it++) {
            int e = tid + it * 256;
            int row = e >> 4, c4 = e & 15;
            long v = (long)v0 + row;
            float4 val = (v < Vv) ? ge[v * 32 + kc * 16 + c4]
                                  : make_float4(0.f, 0.f, 0.f, 0.f);
            *(float4*)(sB + row * CPITCH + c4 * 4) = val;
        }
        __syncthreads();

        const float* pA = sA + (wm * 32 + g) * CPITCH + tg;
        const float* pBs = sB + (wn * 32 + g) * CPITCH + tg;

#pragma unroll
        for (int ks = 0; ks < 8; ks++) {
            int k0 = ks * 8;
            uint32_t ah[2][4], al[2][4];
#pragma unroll
            for (int mt = 0; mt < 2; mt++) {
                const float* pr = pA + mt * 16 * CPITCH;
                tf32_mask_split(pr[k0],                  ah[mt][0], al[mt][0]);
                tf32_mask_split(pr[8 * CPITCH + k0],     ah[mt][1], al[mt][1]);
                tf32_mask_split(pr[k0 + 4],              ah[mt][2], al[mt][2]);
                tf32_mask_split(pr[8 * CPITCH + k0 + 4], ah[mt][3], al[mt][3]);
            }
#pragma unroll
            for (int nt = 0; nt < 4; nt++) {
                const float* pb = pBs + nt * 8 * CPITCH;
                uint32_t bh0, bl0, bh1, bl1;
                tf32_mask_split(pb[k0],     bh0, bl0);
                tf32_mask_split(pb[k0 + 4], bh1, bl1);
#pragma unroll
                for (int mt = 0; mt < 2; mt++) {
                    MMA_TF32(acc[mt][nt], ah[mt][0], ah[mt][1], ah[mt][2], ah[mt][3], bh0, bh1);
                    MMA_TF32(acc[mt][nt], ah[mt][0], ah[mt][1], ah[mt][2], ah[mt][3], bl0, bl1);
                    MMA_TF32(acc[mt][nt], al[mt][0], al[mt][1], al[mt][2], al[mt][3], bh0, bh1);
                }
            }
        }
        __syncthreads();
    }

    // ---- epilogue: ahat stores + exp row-sum atomics ----
#pragma unroll
    for (int mt = 0; mt < 2; mt++) {
        int m = wm * 32 + mt * 16 + g;
        float rs0 = 0.f, rs1 = 0.f;
#pragma unroll
        for (int nt = 0; nt < 4; nt++) {
            int v = v0 + wn * 32 + nt * 8 + 2 * tg;
            if (v < Vv) {
                float c0 = acc[mt][nt][0], c1 = acc[mt][nt][1];
                float c2 = acc[mt][nt][2], c3 = acc[mt][nt][3];
                *(float2*)(ahat + (long)m * Vv + v) = make_float2(c0, c1);
                *(float2*)(ahat + (long)(m + 8) * Vv + v) = make_float2(c2, c3);
                if (do_proba) {
                    rs0 += __expf(c0) + __expf(c1);
                    rs1 += __expf(c2) + __expf(c3);
                }
            }
        }
        if (do_proba) {
            rs0 += __shfl_xor_sync(0xffffffffu, rs0, 1);
            rs0 += __shfl_xor_sync(0xffffffffu, rs0, 2);
            rs1 += __shfl_xor_sync(0xffffffffu, rs1, 1);
            rs1 += __shfl_xor_sync(0xffffffffu, rs1, 2);
            if (tg == 0) {
                atomicAdd(&g_rowsum[m], rs0);
                atomicAdd(&g_rowsum[m + 8], rs1);
            }
        }
    }
}

// ============================================================
// Kernel 4: proba = exp(ahat) / rowsum. grid=(B, 8) x 256 threads:
// 1024 CTAs so every SM has work (was 128 CTAs, issue=22%).
// ============================================================
#define EXP_SPLIT 8
#define CHUNK4 ((Vv / 4 + EXP_SPLIT - 1) / EXP_SPLIT)   // float4s per sub-block

__global__ void __launch_bounds__(256) k_expnorm(
        const float* __restrict__ ahat, float* __restrict__ proba) {
    int b = blockIdx.x;
    int part = blockIdx.y;
    float inv = 1.f / g_rowsum[b];
    const float4* a = (const float4*)(ahat + (long)b * Vv);
    float4* p = (float4*)(proba + (long)b * Vv);
    int lo = part * CHUNK4;
    int hi = lo + CHUNK4;
    if (hi > Vv / 4) hi = Vv / 4;
    for (int v = lo + threadIdx.x; v < hi; v += 256) {
        float4 r = a[v];
        float4 e;
        e.x = __expf(r.x) * inv;
        e.y = __expf(r.y) * inv;
        e.z = __expf(r.z) * inv;
        e.w = __expf(r.w) * inv;
        p[v] = e;
    }
}

// ============================================================
extern "C" void kernel_launch(void* const* d_in, const int* in_sizes, int n_in,
                              void* d_out, int out_size) {
    const int* story = nullptr;
    const int* query = nullptr;
    const float* E = nullptr;
    const float* T = nullptr;
    for (int i = 0; i < n_in; i++) {
        long n = in_sizes[i];
        if (n == (long)Bb * Mm * Ss) story = (const int*)d_in[i];
        else if (n == (long)Bb * Qq) query = (const int*)d_in[i];
        else if (n == (long)NT * Vv * Dd) E = (const float*)d_in[i];
        else if (n == (long)NT * Mm * Dd) T = (const float*)d_in[i];
    }
    float* out = (float*)d_out;
    long BV = (long)Bb * Vv;
    int do_proba = ((long)out_size >= 2 * BV) ? 1 : 0;
    float* proba = out + BV;

    long nwarps = (long)NT * Bb * Mm;
    k_story_sums<<<(int)(nwarps / SS_WPB), SS_WPB * 32>>>(story, E, T);
    k_hops<<<Bb, 1024>>>(query, E);

    const float* E3 = E + (long)(NT - 1) * Vv * Dd;
    cudaFuncSetAttribute(k_gemm_mma, cudaFuncAttributeMaxDynamicSharedMemorySize,
                         GSM4);
    k_gemm_mma<<<(Vv + 63) / 64, 256, GSM4>>>(E3, out, do_proba);

    if (do_proba) {
        dim3 gdim(Bb, EXP_SPLIT);
        k_expnorm<<<gdim, 256>>>(out, proba);
    }
}

// round 13
// speedup vs baseline: 1.0136x; 1.0136x over previous
#include <cuda_runtime.h>
#include <math.h>
#include <stdint.h>

#define Bb 128
#define Mm 200
#define Ss 20
#define Qq 20
#define Vv 50000
#define Dd 128
#define NT 4          // max_hops + 1 tables

// -------- device scratch (static allocation; no cudaMalloc allowed) --------
__device__ float g_u[Bb * Dd];                              // 64 KB
__device__ float g_mt[(long)NT * Bb * Mm * Dd];             // 52.4 MB
__device__ float g_rowsum[Bb];                              // softmax denominators

// ============================================================
// Kernel 1: mt[t][b][i][d] = sum_s E[t][story[b,i,s]][d] + T[t][i][d]
// One warp per (t,b,i), table-major grid (one table hot in L2 at a time).
// ============================================================
#define SS_WPB 8
__global__ void __launch_bounds__(SS_WPB * 32) k_story_sums(
        const int* __restrict__ story,
        const float* __restrict__ E,
        const float* __restrict__ T) {
    long gw = (long)blockIdx.x * SS_WPB + (threadIdx.x >> 5);
    int lane = threadIdx.x & 31;
    int t = (int)(gw / ((long)Bb * Mm));
    int rem = (int)(gw - (long)t * Bb * Mm);
    int b = rem / Mm, i = rem - b * Mm;

    int tok = (lane < Ss) ? story[((long)b * Mm + i) * Ss + lane] : 0;

    const float4* Et = (const float4*)(E + (long)t * Vv * Dd);
    float4 acc = ((const float4*)(T + ((long)t * Mm + i) * Dd))[lane];
#pragma unroll
    for (int s = 0; s < Ss; s++) {
        int id = __shfl_sync(0xffffffffu, tok, s);
        float4 r = Et[(long)id * 32 + lane];
        acc.x += r.x; acc.y += r.y; acc.z += r.z; acc.w += r.w;
    }
    ((float4*)(g_mt + (((long)t * Bb + b) * Mm + i) * Dd))[lane] = acc;
}

// ============================================================
// Kernel 2: query embedding + all 3 hops fused. grid=B, block=1024.
// Also zeroes g_rowsum (block 0) for the epilogue atomics.
// ============================================================
__global__ void __launch_bounds__(1024) k_hops(
        const int* __restrict__ query,
        const float* __restrict__ E) {
    __shared__ float su[Dd];
    __shared__ float sc[Mm];
    __shared__ float red[32];
    __shared__ float bc[2];
    __shared__ float op[1024];
    int b = blockIdx.x, tid = threadIdx.x;
    int w = tid >> 5, lane = tid & 31;

    if (b == 0 && tid < Bb) g_rowsum[tid] = 0.f;   // reset denominators

    // ---- u = sum over query tokens of E[0] rows (fused) ----
    {
        __shared__ int q[Qq];
        if (tid < Qq) q[tid] = query[b * Qq + tid];
        __syncthreads();
        if (tid < Dd) {
            float acc = 0.f;
#pragma unroll
            for (int i = 0; i < Qq; i++)
                acc += E[(long)q[i] * Dd + tid];
            su[tid] = acc;
        }
    }
    __syncthreads();

    for (int hop = 0; hop < NT - 1; hop++) {
        const float* mt = g_mt + (((long)hop * Bb + b) * Mm) * Dd;
        float4 uu = ((const float4*)su)[lane];
        for (int i = w; i < Mm; i += 32) {
            const float4* row = (const float4*)(mt + (long)i * Dd);
            float4 r = row[lane];
            float p = r.x * uu.x + r.y * uu.y + r.z * uu.z + r.w * uu.w;
#pragma unroll
            for (int o = 16; o; o >>= 1) p += __shfl_xor_sync(0xffffffffu, p, o);
            if (lane == 0) sc[i] = p;
        }
        __syncthreads();

        float v = (tid < Mm) ? sc[tid] : -INFINITY;
        float m = v;
#pragma unroll
        for (int o = 16; o; o >>= 1) m = fmaxf(m, __shfl_xor_sync(0xffffffffu, m, o));
        if (lane == 0) red[w] = m;
        __syncthreads();
        if (w == 0) {
            float t = red[lane];
#pragma unroll
            for (int o = 16; o; o >>= 1) t = fmaxf(t, __shfl_xor_sync(0xffffffffu, t, o));
            if (lane == 0) bc[0] = t;
        }
        __syncthreads();
        float e = (tid < Mm) ? expf(v - bc[0]) : 0.f;
        float s = e;
#pragma unroll
        for (int o = 16; o; o >>= 1) s += __shfl_xor_sync(0xffffffffu, s, o);
        if (lane == 0) red[w] = s;
        __syncthreads();
        if (w == 0) {
            float t = red[lane];
#pragma unroll
            for (int o = 16; o; o >>= 1) t += __shfl_xor_sync(0xffffffffu, t, o);
            if (lane == 0) bc[1] = 1.f / t;
        }
        __syncthreads();
        if (tid < Mm) sc[tid] = e * bc[1];
        __syncthreads();

        const float* mtn = g_mt + (((long)(hop + 1) * Bb + b) * Mm) * Dd;
        int part = tid >> 7, d = tid & 127;
        float acc = 0.f;
        int i0 = part * 25;
#pragma unroll
        for (int i = i0; i < i0 + 25; i++)
            acc += sc[i] * mtn[(long)i * Dd + d];
        op[tid] = acc;
        __syncthreads();
        if (tid < Dd) {
            float o = 0.f;
#pragma unroll
            for (int p = 0; p < 8; p++) o += op[p * 128 + tid];
            su[tid] += o;
        }
        __syncthreads();
    }
    if (tid < Dd) g_u[b * Dd + tid] = su[tid];
}

// ============================================================
// tf32 split via bitmask (LOP3 + FADD; no cvt).
// ============================================================
__device__ __forceinline__ void tf32_mask_split(float x, uint32_t& hi, uint32_t& lo) {
    hi = __float_as_uint(x) & 0xFFFFE000u;
    lo = __float_as_uint(x - __uint_as_float(hi));
}
#define MMA_TF32(c, a0, a1, a2, a3, b0, b1) \
    asm volatile("mma.sync.aligned.m16n8k8.row.col.f32.tf32.tf32.f32 " \
        "{%0,%1,%2,%3}, {%4,%5,%6,%7}, {%8,%9}, {%0,%1,%2,%3};" \
        : "+f"((c)[0]), "+f"((c)[1]), "+f"((c)[2]), "+f"((c)[3]) \
        : "r"(a0), "r"(a1), "r"(a2), "r"(a3), "r"(b0), "r"(b1))

// ============================================================
// Kernel 3: ahat = u @ E3^T, 3xTF32 mma (mask-split), K chunked 2x64,
// 3 CTAs/SM (R11 config — 4 CTAs spilled and regressed). Epilogue:
// ahat stores + exp row-sum atomics.
// ============================================================
#define KC 64
#define CPITCH (KC + 4)
#define GSM4 ((128 + 64) * CPITCH * 4)   // 52,224 B

__global__ void __launch_bounds__(256, 3)
k_gemm_mma(const float* __restrict__ E3, float* __restrict__ ahat,
           int do_proba) {
    extern __shared__ float sm[];
    float* sA = sm;                     // [128][CPITCH]
    float* sB = sm + 128 * CPITCH;      // [64][CPITCH]
    int tid = threadIdx.x, lane = tid & 31, wid = tid >> 5;
    int wm = wid & 3, wn = wid >> 2;
    int v0 = blockIdx.x * 64;

    float acc[2][4][4];
#pragma unroll
    for (int i = 0; i < 2; i++)
#pragma unroll
        for (int j = 0; j < 4; j++)
#pragma unroll
            for (int k = 0; k < 4; k++) acc[i][j][k] = 0.f;

    int g = lane >> 2, tg = lane & 3;
    const float4* gu = (const float4*)g_u;
    const float4* ge = (const float4*)E3;

#pragma unroll
    for (int kc = 0; kc < 2; kc++) {
#pragma unroll
        for (int it = 0; it < 8; it++) {
            int e = tid + it * 256;
            int row = e >> 4, c4 = e & 15;
            *(float4*)(sA + row * CPITCH + c4 * 4) = gu[row * 32 + kc * 16 + c4];
        }
#pragma unroll
        for (int it = 0; it < 4; it++) {
            int e = tid + it * 256;
            int row = e >> 4, c4 = e & 15;
            long v = (long)v0 + row;
            float4 val = (v < Vv) ? ge[v * 32 + kc * 16 + c4]
                                  : make_float4(0.f, 0.f, 0.f, 0.f);
            *(float4*)(sB + row * CPITCH + c4 * 4) = val;
        }
        __syncthreads();

        const float* pA = sA + (wm * 32 + g) * CPITCH + tg;
        const float* pBs = sB + (wn * 32 + g) * CPITCH + tg;

#pragma unroll
        for (int ks = 0; ks < 8; ks++) {
            int k0 = ks * 8;
            uint32_t ah[2][4], al[2][4];
#pragma unroll
            for (int mt = 0; mt < 2; mt++) {
                const float* pr = pA + mt * 16 * CPITCH;
                tf32_mask_split(pr[k0],                  ah[mt][0], al[mt][0]);
                tf32_mask_split(pr[8 * CPITCH + k0],     ah[mt][1], al[mt][1]);
                tf32_mask_split(pr[k0 + 4],              ah[mt][2], al[mt][2]);
                tf32_mask_split(pr[8 * CPITCH + k0 + 4], ah[mt][3], al[mt][3]);
            }
#pragma unroll
            for (int nt = 0; nt < 4; nt++) {
                const float* pb = pBs + nt * 8 * CPITCH;
                uint32_t bh0, bl0, bh1, bl1;
                tf32_mask_split(pb[k0],     bh0, bl0);
                tf32_mask_split(pb[k0 + 4], bh1, bl1);
#pragma unroll
                for (int mt = 0; mt < 2; mt++) {
                    MMA_TF32(acc[mt][nt], ah[mt][0], ah[mt][1], ah[mt][2], ah[mt][3], bh0, bh1);
                    MMA_TF32(acc[mt][nt], ah[mt][0], ah[mt][1], ah[mt][2], ah[mt][3], bl0, bl1);
                    MMA_TF32(acc[mt][nt], al[mt][0], al[mt][1], al[mt][2], al[mt][3], bh0, bh1);
                }
            }
        }
        __syncthreads();
    }

    // ---- epilogue: ahat stores + exp row-sum atomics ----
#pragma unroll
    for (int mt = 0; mt < 2; mt++) {
        int m = wm * 32 + mt * 16 + g;
        float rs0 = 0.f, rs1 = 0.f;
#pragma unroll
        for (int nt = 0; nt < 4; nt++) {
            int v = v0 + wn * 32 + nt * 8 + 2 * tg;
            if (v < Vv) {
                float c0 = acc[mt][nt][0], c1 = acc[mt][nt][1];
                float c2 = acc[mt][nt][2], c3 = acc[mt][nt][3];
                *(float2*)(ahat + (long)m * Vv + v) = make_float2(c0, c1);
                *(float2*)(ahat + (long)(m + 8) * Vv + v) = make_float2(c2, c3);
                if (do_proba) {
                    rs0 += __expf(c0) + __expf(c1);
                    rs1 += __expf(c2) + __expf(c3);
                }
            }
        }
        if (do_proba) {
            rs0 += __shfl_xor_sync(0xffffffffu, rs0, 1);
            rs0 += __shfl_xor_sync(0xffffffffu, rs0, 2);
            rs1 += __shfl_xor_sync(0xffffffffu, rs1, 1);
            rs1 += __shfl_xor_sync(0xffffffffu, rs1, 2);
            if (tg == 0) {
                atomicAdd(&g_rowsum[m], rs0);
                atomicAdd(&g_rowsum[m + 8], rs1);
            }
        }
    }
}

// ============================================================
// Kernel 4: proba = exp(ahat) / rowsum. grid=(B, 8) x 256 threads
// (1024 CTAs). Loads batched 2-wide ahead of MUFU+STG for higher MLP.
// ============================================================
#define EXP_SPLIT 8
#define CHUNK4 ((Vv / 4 + EXP_SPLIT - 1) / EXP_SPLIT)   // float4s per sub-block

__global__ void __launch_bounds__(256) k_expnorm(
        const float* __restrict__ ahat, float* __restrict__ proba) {
    int b = blockIdx.x;
    int part = blockIdx.y;
    float inv = 1.f / g_rowsum[b];
    const float4* a = (const float4*)(ahat + (long)b * Vv);
    float4* p = (float4*)(proba + (long)b * Vv);
    int lo = part * CHUNK4;
    int hi = lo + CHUNK4;
    if (hi > Vv / 4) hi = Vv / 4;

    int v = lo + threadIdx.x;
    // batched pairs: issue both loads before any exp/store
    for (; v + 256 < hi; v += 512) {
        float4 r0 = a[v];
        float4 r1 = a[v + 256];
        float4 e0, e1;
        e0.x = __expf(r0.x) * inv; e0.y = __expf(r0.y) * inv;
        e0.z = __expf(r0.z) * inv; e0.w = __expf(r0.w) * inv;
        e1.x = __expf(r1.x) * inv; e1.y = __expf(r1.y) * inv;
        e1.z = __expf(r1.z) * inv; e1.w = __expf(r1.w) * inv;
        p[v] = e0;
        p[v + 256] = e1;
    }
    for (; v < hi; v += 256) {
        float4 r = a[v];
        float4 e;
        e.x = __expf(r.x) * inv; e.y = __expf(r.y) * inv;
        e.z = __expf(r.z) * inv; e.w = __expf(r.w) * inv;
        p[v] = e;
    }
}

// ============================================================
extern "C" void kernel_launch(void* const* d_in, const int* in_sizes, int n_in,
                              void* d_out, int out_size) {
    const int* story = nullptr;
    const int* query = nullptr;
    const float* E = nullptr;
    const float* T = nullptr;
    for (int i = 0; i < n_in; i++) {
        long n = in_sizes[i];
        if (n == (long)Bb * Mm * Ss) story = (const int*)d_in[i];
        else if (n == (long)Bb * Qq) query = (const int*)d_in[i];
        else if (n == (long)NT * Vv * Dd) E = (const float*)d_in[i];
        else if (n == (long)NT * Mm * Dd) T = (const float*)d_in[i];
    }
    float* out = (float*)d_out;
    long BV = (long)Bb * Vv;
    int do_proba = ((long)out_size >= 2 * BV) ? 1 : 0;
    float* proba = out + BV;

    long nwarps = (long)NT * Bb * Mm;
    k_story_sums<<<(int)(nwarps / SS_WPB), SS_WPB * 32>>>(story, E, T);
    k_hops<<<Bb, 1024>>>(query, E);

    const float* E3 = E + (long)(NT - 1) * Vv * Dd;
    cudaFuncSetAttribute(k_gemm_mma, cudaFuncAttributeMaxDynamicSharedMemorySize,
                         GSM4);
    k_gemm_mma<<<(Vv + 63) / 64, 256, GSM4>>>(E3, out, do_proba);

    if (do_proba) {
        dim3 gdim(Bb, EXP_SPLIT);
        k_expnorm<<<gdim, 256>>>(out, proba);
    }
}

// round 14
// speedup vs baseline: 1.0939x; 1.0792x over previous
#include <cuda_runtime.h>
#include <math.h>
#include <stdint.h>

#define Bb 128
#define Mm 200
#define Ss 20
#define Qq 20
#define Vv 50000
#define Dd 128
#define NT 4          // max_hops + 1 tables

// -------- device scratch (static allocation; no cudaMalloc allowed) --------
__device__ float g_u[Bb * Dd];                              // 64 KB
__device__ float g_mt[(long)NT * Bb * Mm * Dd];             // 52.4 MB
__device__ float g_rowsum[Bb];                              // softmax denominators

// ============================================================
// Kernel 1: mt[t][b][i][d] = sum_s E[t][story[b,i,s]][d] + T[t][i][d]
// One warp per (t,b,i), table-major grid.
// ============================================================
#define SS_WPB 8
__global__ void __launch_bounds__(SS_WPB * 32) k_story_sums(
        const int* __restrict__ story,
        const float* __restrict__ E,
        const float* __restrict__ T) {
    long gw = (long)blockIdx.x * SS_WPB + (threadIdx.x >> 5);
    int lane = threadIdx.x & 31;
    int t = (int)(gw / ((long)Bb * Mm));
    int rem = (int)(gw - (long)t * Bb * Mm);
    int b = rem / Mm, i = rem - b * Mm;

    int tok = (lane < Ss) ? story[((long)b * Mm + i) * Ss + lane] : 0;

    const float4* Et = (const float4*)(E + (long)t * Vv * Dd);
    float4 acc = ((const float4*)(T + ((long)t * Mm + i) * Dd))[lane];
#pragma unroll
    for (int s = 0; s < Ss; s++) {
        int id = __shfl_sync(0xffffffffu, tok, s);
        float4 r = Et[(long)id * 32 + lane];
        acc.x += r.x; acc.y += r.y; acc.z += r.z; acc.w += r.w;
    }
    ((float4*)(g_mt + (((long)t * Bb + b) * Mm + i) * Dd))[lane] = acc;
}

// ============================================================
// Kernel 2: query embedding + all 3 hops fused. grid=B, block=1024.
// Also zeroes g_rowsum (block 0).
// ============================================================
__global__ void __launch_bounds__(1024) k_hops(
        const int* __restrict__ query,
        const float* __restrict__ E) {
    __shared__ float su[Dd];
    __shared__ float sc[Mm];
    __shared__ float red[32];
    __shared__ float bc[2];
    __shared__ float op[1024];
    int b = blockIdx.x, tid = threadIdx.x;
    int w = tid >> 5, lane = tid & 31;

    if (b == 0 && tid < Bb) g_rowsum[tid] = 0.f;

    {
        __shared__ int q[Qq];
        if (tid < Qq) q[tid] = query[b * Qq + tid];
        __syncthreads();
        if (tid < Dd) {
            float acc = 0.f;
#pragma unroll
            for (int i = 0; i < Qq; i++)
                acc += E[(long)q[i] * Dd + tid];
            su[tid] = acc;
        }
    }
    __syncthreads();

    for (int hop = 0; hop < NT - 1; hop++) {
        const float* mt = g_mt + (((long)hop * Bb + b) * Mm) * Dd;
        float4 uu = ((const float4*)su)[lane];
        for (int i = w; i < Mm; i += 32) {
            const float4* row = (const float4*)(mt + (long)i * Dd);
            float4 r = row[lane];
            float p = r.x * uu.x + r.y * uu.y + r.z * uu.z + r.w * uu.w;
#pragma unroll
            for (int o = 16; o; o >>= 1) p += __shfl_xor_sync(0xffffffffu, p, o);
            if (lane == 0) sc[i] = p;
        }
        __syncthreads();

        float v = (tid < Mm) ? sc[tid] : -INFINITY;
        float m = v;
#pragma unroll
        for (int o = 16; o; o >>= 1) m = fmaxf(m, __shfl_xor_sync(0xffffffffu, m, o));
        if (lane == 0) red[w] = m;
        __syncthreads();
        if (w == 0) {
            float t = red[lane];
#pragma unroll
            for (int o = 16; o; o >>= 1) t = fmaxf(t, __shfl_xor_sync(0xffffffffu, t, o));
            if (lane == 0) bc[0] = t;
        }
        __syncthreads();
        float e = (tid < Mm) ? expf(v - bc[0]) : 0.f;
        float s = e;
#pragma unroll
        for (int o = 16; o; o >>= 1) s += __shfl_xor_sync(0xffffffffu, s, o);
        if (lane == 0) red[w] = s;
        __syncthreads();
        if (w == 0) {
            float t = red[lane];
#pragma unroll
            for (int o = 16; o; o >>= 1) t += __shfl_xor_sync(0xffffffffu, t, o);
            if (lane == 0) bc[1] = 1.f / t;
        }
        __syncthreads();
        if (tid < Mm) sc[tid] = e * bc[1];
        __syncthreads();

        const float* mtn = g_mt + (((long)(hop + 1) * Bb + b) * Mm) * Dd;
        int part = tid >> 7, d = tid & 127;
        float acc = 0.f;
        int i0 = part * 25;
#pragma unroll
        for (int i = i0; i < i0 + 25; i++)
            acc += sc[i] * mtn[(long)i * Dd + d];
        op[tid] = acc;
        __syncthreads();
        if (tid < Dd) {
            float o = 0.f;
#pragma unroll
            for (int p = 0; p < 8; p++) o += op[p * 128 + tid];
            su[tid] += o;
        }
        __syncthreads();
    }
    if (tid < Dd) g_u[b * Dd + tid] = su[tid];
}

// ============================================================
// bf16x2 truncation split: for a float pair (x0,x1) produce packed
// bf16x2 hi (top 16 bits of each, via PRMT byte-pick) and bf16x2 lo
// (x - hi, exact subtraction, then top-16 pick). Error ~2^-17.
// ============================================================
__device__ __forceinline__ void bf16x2_split(float2 x, uint32_t& h, uint32_t& l) {
    uint32_t x0 = __float_as_uint(x.x), x1 = __float_as_uint(x.y);
    float l0 = x.x - __uint_as_float(x0 & 0xFFFF0000u);
    float l1 = x.y - __uint_as_float(x1 & 0xFFFF0000u);
    uint32_t lo0 = __float_as_uint(l0), lo1 = __float_as_uint(l1);
    asm("prmt.b32 %0, %1, %2, 0x7632;" : "=r"(h) : "r"(x0), "r"(x1));
    asm("prmt.b32 %0, %1, %2, 0x7632;" : "=r"(l) : "r"(lo0), "r"(lo1));
}
#define MMA_BF16(c, a0, a1, a2, a3, b0, b1) \
    asm volatile("mma.sync.aligned.m16n8k16.row.col.f32.bf16.bf16.f32 " \
        "{%0,%1,%2,%3}, {%4,%5,%6,%7}, {%8,%9}, {%0,%1,%2,%3};" \
        : "+f"((c)[0]), "+f"((c)[1]), "+f"((c)[2]), "+f"((c)[3]) \
        : "r"(a0), "r"(a1), "r"(a2), "r"(a3), "r"(b0), "r"(b1))

// ============================================================
// Kernel 3: ahat = u @ E3^T via 3xBF16 m16n8k16 mma (truncation split).
// Block 128M x 64N, 256 thr (8 warps 4Mx2N), K chunked 2x64, 3 CTAs/SM.
// CPITCH=72: conflict-free LDS.64 fragment loads (banks 8g+2tg distinct).
// Epilogue: ahat stores + exp row-sum atomics.
// ============================================================
#define KC 64
#define CPITCH 72
#define GSM4 ((128 + 64) * CPITCH * 4)   // 55,296 B

__global__ void __launch_bounds__(256, 3)
k_gemm_mma(const float* __restrict__ E3, float* __restrict__ ahat,
           int do_proba) {
    extern __shared__ float sm[];
    float* sA = sm;                     // [128][CPITCH]
    float* sB = sm + 128 * CPITCH;      // [64][CPITCH]
    int tid = threadIdx.x, lane = tid & 31, wid = tid >> 5;
    int wm = wid & 3, wn = wid >> 2;
    int v0 = blockIdx.x * 64;

    float acc[2][4][4];
#pragma unroll
    for (int i = 0; i < 2; i++)
#pragma unroll
        for (int j = 0; j < 4; j++)
#pragma unroll
            for (int k = 0; k < 4; k++) acc[i][j][k] = 0.f;

    int g = lane >> 2, tg = lane & 3;
    const float4* gu = (const float4*)g_u;
    const float4* ge = (const float4*)E3;

#pragma unroll
    for (int kc = 0; kc < 2; kc++) {
#pragma unroll
        for (int it = 0; it < 8; it++) {
            int e = tid + it * 256;
            int row = e >> 4, c4 = e & 15;
            *(float4*)(sA + row * CPITCH + c4 * 4) = gu[row * 32 + kc * 16 + c4];
        }
#pragma unroll
        for (int it = 0; it < 4; it++) {
            int e = tid + it * 256;
            int row = e >> 4, c4 = e & 15;
            long v = (long)v0 + row;
            float4 val = (v < Vv) ? ge[v * 32 + kc * 16 + c4]
                                  : make_float4(0.f, 0.f, 0.f, 0.f);
            *(float4*)(sB + row * CPITCH + c4 * 4) = val;
        }
        __syncthreads();

        const float* pA = sA + (wm * 32 + g) * CPITCH + 2 * tg;
        const float* pBs = sB + (wn * 32 + g) * CPITCH + 2 * tg;

#pragma unroll
        for (int ks = 0; ks < 4; ks++) {
            int k0 = ks * 16;
            // A fragments (2 m-tiles): 4 float2 loads each, split to bf16x2
            uint32_t ah[2][4], al[2][4];
#pragma unroll
            for (int mt = 0; mt < 2; mt++) {
                const float* pr = pA + mt * 16 * CPITCH;
                float2 p0 = *(const float2*)(pr + k0);
                float2 p1 = *(const float2*)(pr + 8 * CPITCH + k0);
                float2 p2 = *(const float2*)(pr + k0 + 8);
                float2 p3 = *(const float2*)(pr + 8 * CPITCH + k0 + 8);
                bf16x2_split(p0, ah[mt][0], al[mt][0]);
                bf16x2_split(p1, ah[mt][1], al[mt][1]);
                bf16x2_split(p2, ah[mt][2], al[mt][2]);
                bf16x2_split(p3, ah[mt][3], al[mt][3]);
            }
#pragma unroll
            for (int nt = 0; nt < 4; nt++) {
                const float* pb = pBs + nt * 8 * CPITCH;
                float2 q0 = *(const float2*)(pb + k0);
                float2 q1 = *(const float2*)(pb + k0 + 8);
                uint32_t bh0, bl0, bh1, bl1;
                bf16x2_split(q0, bh0, bl0);
                bf16x2_split(q1, bh1, bl1);
#pragma unroll
                for (int mt = 0; mt < 2; mt++) {
                    MMA_BF16(acc[mt][nt], ah[mt][0], ah[mt][1], ah[mt][2], ah[mt][3], bh0, bh1);
                    MMA_BF16(acc[mt][nt], ah[mt][0], ah[mt][1], ah[mt][2], ah[mt][3], bl0, bl1);
                    MMA_BF16(acc[mt][nt], al[mt][0], al[mt][1], al[mt][2], al[mt][3], bh0, bh1);
                }
            }
        }
        __syncthreads();
    }

    // ---- epilogue: ahat stores + exp row-sum atomics ----
#pragma unroll
    for (int mt = 0; mt < 2; mt++) {
        int m = wm * 32 + mt * 16 + g;
        float rs0 = 0.f, rs1 = 0.f;
#pragma unroll
        for (int nt = 0; nt < 4; nt++) {
            int v = v0 + wn * 32 + nt * 8 + 2 * tg;
            if (v < Vv) {
                float c0 = acc[mt][nt][0], c1 = acc[mt][nt][1];
                float c2 = acc[mt][nt][2], c3 = acc[mt][nt][3];
                *(float2*)(ahat + (long)m * Vv + v) = make_float2(c0, c1);
                *(float2*)(ahat + (long)(m + 8) * Vv + v) = make_float2(c2, c3);
                if (do_proba) {
                    rs0 += __expf(c0) + __expf(c1);
                    rs1 += __expf(c2) + __expf(c3);
                }
            }
        }
        if (do_proba) {
            rs0 += __shfl_xor_sync(0xffffffffu, rs0, 1);
            rs0 += __shfl_xor_sync(0xffffffffu, rs0, 2);
            rs1 += __shfl_xor_sync(0xffffffffu, rs1, 1);
            rs1 += __shfl_xor_sync(0xffffffffu, rs1, 2);
            if (tg == 0) {
                atomicAdd(&g_rowsum[m], rs0);
                atomicAdd(&g_rowsum[m + 8], rs1);
            }
        }
    }
}

// ============================================================
// Kernel 4: proba = exp(ahat) / rowsum. grid=(B, 8) x 256 threads
// (1024 CTAs). Simple loop (R12 version — manual batching regressed).
// ============================================================
#define EXP_SPLIT 8
#define CHUNK4 ((Vv / 4 + EXP_SPLIT - 1) / EXP_SPLIT)

__global__ void __launch_bounds__(256) k_expnorm(
        const float* __restrict__ ahat, float* __restrict__ proba) {
    int b = blockIdx.x;
    int part = blockIdx.y;
    float inv = 1.f / g_rowsum[b];
    const float4* a = (const float4*)(ahat + (long)b * Vv);
    float4* p = (float4*)(proba + (long)b * Vv);
    int lo = part * CHUNK4;
    int hi = lo + CHUNK4;
    if (hi > Vv / 4) hi = Vv / 4;
    for (int v = lo + threadIdx.x; v < hi; v += 256) {
        float4 r = a[v];
        float4 e;
        e.x = __expf(r.x) * inv;
        e.y = __expf(r.y) * inv;
        e.z = __expf(r.z) * inv;
        e.w = __expf(r.w) * inv;
        p[v] = e;
    }
}

// ============================================================
extern "C" void kernel_launch(void* const* d_in, const int* in_sizes, int n_in,
                              void* d_out, int out_size) {
    const int* story = nullptr;
    const int* query = nullptr;
    const float* E = nullptr;
    const float* T = nullptr;
    for (int i = 0; i < n_in; i++) {
        long n = in_sizes[i];
        if (n == (long)Bb * Mm * Ss) story = (const int*)d_in[i];
        else if (n == (long)Bb * Qq) query = (const int*)d_in[i];
        else if (n == (long)NT * Vv * Dd) E = (const float*)d_in[i];
        else if (n == (long)NT * Mm * Dd) T = (const float*)d_in[i];
    }
    float* out = (float*)d_out;
    long BV = (long)Bb * Vv;
    int do_proba = ((long)out_size >= 2 * BV) ? 1 : 0;
    float* proba = out + BV;

    long nwarps = (long)NT * Bb * Mm;
    k_story_sums<<<(int)(nwarps / SS_WPB), SS_WPB * 32>>>(story, E, T);
    k_hops<<<Bb, 1024>>>(query, E);

    const float* E3 = E + (long)(NT - 1) * Vv * Dd;
    cudaFuncSetAttribute(k_gemm_mma, cudaFuncAttributeMaxDynamicSharedMemorySize,
                         GSM4);
    k_gemm_mma<<<(Vv + 63) / 64, 256, GSM4>>>(E3, out, do_proba);

    if (do_proba) {
        dim3 gdim(Bb, EXP_SPLIT);
        k_expnorm<<<gdim, 256>>>(out, proba);
    }
}